// round 13
// baseline (speedup 1.0000x reference)
#include <cuda_runtime.h>
#include <cuda_bf16.h>
#include <cstdint>
#include <cstddef>

#define BATCH 8
#define CDIM 768
#define HWN 4096
#define MT (BATCH*HWN)   // 32768 tokens
#define NH 12
#define HD 64
#define HID 3072

// ------------------- scratch (static device globals; no allocs) -------------------
__device__ float          g_tok[(size_t)MT*CDIM];
__device__ __nv_bfloat16  g_xn [(size_t)MT*CDIM];
__device__ __nv_bfloat16  g_qkv[(size_t)MT*3*CDIM];
__device__ float          g_kvp[2*BATCH*NH*HD*HD];    // split-2 partial kv
__device__ __nv_bfloat16  g_o  [(size_t)MT*CDIM];
__device__ __nv_bfloat16  g_hb [(size_t)MT*HID];
// transposed bf16 weights: (N, K) row-major (each row: K contiguous)
__device__ __nv_bfloat16  g_wqkv[(size_t)3*CDIM*CDIM];
__device__ __nv_bfloat16  g_wout[(size_t)CDIM*CDIM];
__device__ __nv_bfloat16  g_w1  [(size_t)HID*CDIM];
__device__ __nv_bfloat16  g_w2  [(size_t)CDIM*HID];

// ------------------- helpers -------------------
__device__ __forceinline__ float phi_fn(float x) { return x > 0.f ? x + 1.f : __expf(x); }
__device__ __forceinline__ float gelu_fn(float x) {
    return 0.5f * x * (1.f + erff(x * 0.70710678118654752f));
}
__device__ __forceinline__ uint32_t smem_u32(const void* p) {
    uint32_t a;
    asm("{ .reg .u64 t; cvta.to.shared.u64 t, %1; cvt.u32.u64 %0, t; }" : "=r"(a) : "l"(p));
    return a;
}
__device__ __forceinline__ void cpa16(uint32_t s, const void* g) {
    asm volatile("cp.async.cg.shared.global [%0], [%1], 16;" :: "r"(s), "l"(g));
}
__device__ __forceinline__ void ldsm4(uint32_t* r, uint32_t addr) {
    asm volatile("ldmatrix.sync.aligned.m8n8.x4.shared.b16 {%0,%1,%2,%3}, [%4];"
                 : "=r"(r[0]), "=r"(r[1]), "=r"(r[2]), "=r"(r[3]) : "r"(addr));
}

// ------------------- weight transpose fp32 (K,N) -> bf16 (N,K) -------------------
__global__ void k_wtrans(const float* __restrict__ w, __nv_bfloat16* __restrict__ wt,
                         int K, int N) {
    __shared__ float t[32][33];
    int k0 = blockIdx.x * 32, n0 = blockIdx.y * 32;
    for (int i = threadIdx.y; i < 32; i += 8)
        t[i][threadIdx.x] = w[(size_t)(k0 + i) * N + n0 + threadIdx.x];
    __syncthreads();
    for (int i = threadIdx.y; i < 32; i += 8)
        wt[(size_t)(n0 + i) * K + k0 + threadIdx.x] = __float2bfloat16(t[threadIdx.x][i]);
}

// ------------------- bicubic taps -------------------
__device__ __forceinline__ void cub_taps(int i, float* w, int* idx) {
    const float a = -0.75f;
    float src = (i + 0.5f) * 0.5f - 0.5f;
    float i0 = floorf(src);
#pragma unroll
    for (int t = 0; t < 4; t++) {
        float p = i0 + (float)(t - 1);
        float d = fabsf(src - p);
        float wt;
        if (d <= 1.f)       wt = ((a + 2.f) * d - (a + 3.f)) * d * d + 1.f;
        else if (d < 2.f)   wt = ((a * d - 5.f * a) * d + 8.f * a) * d - 4.f * a;
        else                wt = 0.f;
        w[t] = wt;
        int ip = (int)floorf(p);
        idx[t] = ip < 0 ? 0 : (ip > 31 ? 31 : ip);
    }
}

// ------------------- fused RPE + tokenize + LayerNorm1 ----------------------------
// Block: 32 tokens x full C=768.  smem tile [32][769] fp32 (stride 769 -> conflict-free).
// Phase 1: transpose-load x + inline bicubic bias -> smem.
// Phase 2: per-token LN over C; write g_tok (fp32) and g_xn (bf16) once.
#define RPELN_SMEM (32*769*4)
__global__ __launch_bounds__(256) void k_rpe_ln(
    const float* __restrict__ x, const float* __restrict__ rel,
    const float* __restrict__ rpe_scale,
    const float* __restrict__ lnw, const float* __restrict__ lnb)
{
    extern __shared__ float sm[];      // [32][769]
    float sc = __ldg(rpe_scale);
    int b = blockIdx.y;
    int n0 = blockIdx.x * 32;
    int lane = threadIdx.x & 31, wrp = threadIdx.x >> 5;   // 32 x 8
    int n = n0 + lane;
    int h = n >> 6, w = n & 63;
    float wh[4], ww[4]; int ih[4], iw[4];
    cub_taps(h, wh, ih);
    cub_taps(w, ww, iw);

    // phase 1: for each c, load x[b,c,n0+lane] (coalesced), add bias, store transposed
    for (int c0 = 0; c0 < CDIM; c0 += 32) {
        for (int i = wrp; i < 32; i += 8) {
            int c = c0 + i;
            const float* rb = rel + (size_t)c * 1024;
            float bias = 0.f;
#pragma unroll
            for (int ti = 0; ti < 4; ti++) {
                float rsum = 0.f;
#pragma unroll
                for (int tj = 0; tj < 4; tj++) rsum += ww[tj] * __ldg(rb + ih[ti] * 32 + iw[tj]);
                bias += wh[ti] * rsum;
            }
            sm[lane * 769 + c] = x[((size_t)b * CDIM + c) * HWN + n] + sc * bias;
        }
    }
    __syncthreads();

    // phase 2: each warp LNs 4 token rows
#pragma unroll 1
    for (int r = 0; r < 4; r++) {
        int nl = wrp * 4 + r;
        float v[24];
        float s = 0.f, ss = 0.f;
#pragma unroll
        for (int j = 0; j < 24; j++) {
            v[j] = sm[nl * 769 + lane + j * 32];
            s += v[j]; ss += v[j] * v[j];
        }
#pragma unroll
        for (int off = 16; off > 0; off >>= 1) {
            s  += __shfl_xor_sync(0xffffffffu, s, off);
            ss += __shfl_xor_sync(0xffffffffu, ss, off);
        }
        float mean = s * (1.f / CDIM);
        float var  = ss * (1.f / CDIM) - mean * mean;
        float rstd = rsqrtf(var + 1e-6f);
        size_t row = ((size_t)b * HWN + n0 + nl) * CDIM;
#pragma unroll
        for (int j = 0; j < 24; j++) {
            int c = lane + j * 32;
            g_tok[row + c] = v[j];
            g_xn[row + c] = __float2bfloat16((v[j] - mean) * rstd * __ldg(lnw + c) + __ldg(lnb + c));
        }
    }
}

// ------------------- LayerNorm C=768 -> bf16 (for LN2) -------------------
__global__ void k_ln(const float* __restrict__ in, const float* __restrict__ w,
                     const float* __restrict__ bb, __nv_bfloat16* __restrict__ out) {
    __shared__ float red[16];
    int m = blockIdx.x;
    int t = threadIdx.x;
    const float* row = in + (size_t)m * CDIM;
    float v0 = row[t], v1 = row[t + 256], v2 = row[t + 512];
    float s = v0 + v1 + v2;
    float ss = v0 * v0 + v1 * v1 + v2 * v2;
#pragma unroll
    for (int off = 16; off > 0; off >>= 1) {
        s  += __shfl_xor_sync(0xffffffffu, s, off);
        ss += __shfl_xor_sync(0xffffffffu, ss, off);
    }
    int warp = t >> 5, lane = t & 31;
    if (lane == 0) { red[warp] = s; red[8 + warp] = ss; }
    __syncthreads();
    if (t < 32) {
        float a = (t < 8) ? red[t] : 0.f;
        float b2 = (t < 8) ? red[8 + t] : 0.f;
#pragma unroll
        for (int off = 4; off > 0; off >>= 1) {
            a  += __shfl_xor_sync(0xffffffffu, a, off);
            b2 += __shfl_xor_sync(0xffffffffu, b2, off);
        }
        if (t == 0) { red[0] = a; red[1] = b2; }
    }
    __syncthreads();
    float mean = red[0] * (1.f / CDIM);
    float var  = red[1] * (1.f / CDIM) - mean * mean;
    float r = rsqrtf(var + 1e-6f);
    __nv_bfloat16* orow = out + (size_t)m * CDIM;
    orow[t]       = __float2bfloat16((v0 - mean) * r * w[t]       + bb[t]);
    orow[t + 256] = __float2bfloat16((v1 - mean) * r * w[t + 256] + bb[t + 256]);
    orow[t + 512] = __float2bfloat16((v2 - mean) * r * w[t + 512] + bb[t + 512]);
}

// ------------------- HMMA GEMM: C(M,N) = A(M,K) @ Bt(N,K)^T -------------------
// 128x128 CTA tile, warp tile 64x32 (2x4 warps), K-step 64,
// 3-stage cp.async ring, ONE __syncthreads per K-step, copy issued BEFORE compute.
// MODE 0: outH = acc + bias[c]                       (bf16)
// MODE 1: outF = resid + gvec[c]*(acc + bias[c])     (fp32, token layout)
// MODE 2: outH = gelu(acc + bias[c])                 (bf16)
// MODE 3: out (B,C,H,W) = resid + gvec[c]*(acc+bias) TRANSPOSED via smem tile
#define ROWB 144u
#define B_OFF 18432u
#define STG_BYTES 36864u
#define GEMM_SMEM (3*36864)

template<int MODE>
__global__ __launch_bounds__(256, 2) void k_gemm(
    const __nv_bfloat16* __restrict__ A, const __nv_bfloat16* __restrict__ Bt,
    const float* __restrict__ bias, const float* __restrict__ gvec,
    const float* __restrict__ resid, float* __restrict__ outF,
    __nv_bfloat16* __restrict__ outH, int K, int N)
{
    extern __shared__ char smem[];
    const uint32_t sbase = smem_u32(smem);
    const int tid = threadIdx.x;
    const int warp = tid >> 5, lane = tid & 31;
    const int wm = warp >> 2, wn = warp & 3;          // 2x4 warps, warp tile 64x32
    const int g = lane >> 2, tig = lane & 3;
    const int bm = blockIdx.y, bn = blockIdx.x;

    float acc[4][4][4];
#pragma unroll
    for (int a = 0; a < 4; a++)
#pragma unroll
        for (int b = 0; b < 4; b++)
#pragma unroll
            for (int c = 0; c < 4; c++) acc[a][b][c] = 0.f;

    const __nv_bfloat16* Ab = A  + (size_t)(bm * 128) * K;
    const __nv_bfloat16* Bb = Bt + (size_t)(bn * 128) * K;
    const int nk = K >> 6;

    const uint32_t aoff = (uint32_t)(wm * 64 + (lane & 15)) * ROWB + (uint32_t)(lane >> 4) * 16;
    const uint32_t boff = B_OFF
                        + (uint32_t)(wn * 32 + (lane & 7) + ((lane >> 4) & 1) * 8) * ROWB
                        + (uint32_t)((lane >> 3) & 1) * 16;

#define COPY_STAGE(buf, k0)                                                          \
    do {                                                                             \
        uint32_t sd = sbase + (uint32_t)(buf) * STG_BYTES;                           \
        _Pragma("unroll")                                                            \
        for (int i = 0; i < 4; i++) {          /* A: 1024 chunks */                  \
            int idx = tid + i * 256; int r = idx >> 3, c4 = idx & 7;                 \
            cpa16(sd + (uint32_t)r * ROWB + (uint32_t)c4 * 16,                       \
                  Ab + (size_t)r * K + (k0) + c4 * 8);                               \
        }                                                                            \
        _Pragma("unroll")                                                            \
        for (int i = 0; i < 4; i++) {          /* B: 1024 chunks */                  \
            int idx = tid + i * 256; int r = idx >> 3, c4 = idx & 7;                 \
            cpa16(sd + B_OFF + (uint32_t)r * ROWB + (uint32_t)c4 * 16,               \
                  Bb + (size_t)r * K + (k0) + c4 * 8);                               \
        }                                                                            \
    } while (0)

    COPY_STAGE(0, 0);
    asm volatile("cp.async.commit_group;" ::: "memory");
    COPY_STAGE(1, 64);
    asm volatile("cp.async.commit_group;" ::: "memory");

    int stg = 0;   // buffer holding stage s
    for (int s = 0; s < nk; s++) {
        asm volatile("cp.async.wait_group 1;" ::: "memory");
        __syncthreads();   // stage s visible; all warps done with buffer (s+2)%3

        int nb = stg + 2; if (nb >= 3) nb -= 3;
        if (s + 2 < nk) COPY_STAGE(nb, (s + 2) << 6);
        asm volatile("cp.async.commit_group;" ::: "memory");   // unconditional: group numbering

        uint32_t sb0 = sbase + (uint32_t)stg * STG_BYTES;
#pragma unroll
        for (int kk = 0; kk < 4; kk++) {        // four k16 sub-steps
            uint32_t af[4][4], bfr[2][4];
#pragma unroll
            for (int mi = 0; mi < 4; mi++)
                ldsm4(af[mi], sb0 + aoff + (uint32_t)(mi * 16) * ROWB + kk * 32);
#pragma unroll
            for (int p = 0; p < 2; p++)
                ldsm4(bfr[p], sb0 + boff + (uint32_t)(p * 16) * ROWB + kk * 32);
#pragma unroll
            for (int mi = 0; mi < 4; mi++)
#pragma unroll
                for (int ni = 0; ni < 4; ni++) {
                    const int p = ni >> 1, q = (ni & 1) * 2;
                    asm volatile(
                        "mma.sync.aligned.m16n8k16.row.col.f32.bf16.bf16.f32 "
                        "{%0,%1,%2,%3}, {%4,%5,%6,%7}, {%8,%9}, {%0,%1,%2,%3};"
                        : "+f"(acc[mi][ni][0]), "+f"(acc[mi][ni][1]),
                          "+f"(acc[mi][ni][2]), "+f"(acc[mi][ni][3])
                        : "r"(af[mi][0]), "r"(af[mi][1]), "r"(af[mi][2]), "r"(af[mi][3]),
                          "r"(bfr[p][q]), "r"(bfr[p][q + 1]));
                }
        }
        stg++; if (stg == 3) stg = 0;
    }
#undef COPY_STAGE

    if (MODE == 3) {
        // transposed epilogue: stage (resid + g*(acc+bias)) tile in smem, write
        // coalesced along n to (B,C,H,W) output. Tile never crosses batch bound.
        float* smf = (float*)smem;
        __syncthreads();   // mainloop smem fully consumed by all warps
#pragma unroll
        for (int mi = 0; mi < 4; mi++) {
            int rl = wm * 64 + mi * 16 + g;
#pragma unroll
            for (int ni = 0; ni < 4; ni++) {
                int cl = wn * 32 + ni * 8 + 2 * tig;
                int c = bn * 128 + cl;
#pragma unroll
                for (int half = 0; half < 2; half++) {
                    int r = rl + 8 * half;
                    float v0 = acc[mi][ni][half * 2 + 0] + __ldg(bias + c);
                    float v1 = acc[mi][ni][half * 2 + 1] + __ldg(bias + c + 1);
                    size_t idx = (size_t)(bm * 128 + r) * N + c;
                    float2 res = *(const float2*)(resid + idx);
                    smf[cl * 132 + r]       = res.x + __ldg(gvec + c)     * v0;
                    smf[(cl + 1) * 132 + r] = res.y + __ldg(gvec + c + 1) * v1;
                }
            }
        }
        __syncthreads();
        int b  = (bm * 128) >> 12;         // /HWN
        int n0 = (bm * 128) & 4095;
#pragma unroll
        for (int i = 0; i < 16; i++) {
            int idx = tid + i * 256;
            int cl = idx >> 5, q = idx & 31;         // each warp: one full c-row
            float4 v = *(float4*)&smf[cl * 132 + q * 4];
            *(float4*)(outF + (((size_t)b * CDIM + bn * 128 + cl) << 12) + n0 + q * 4) = v;
        }
        return;
    }

    // epilogue (MODES 0/1/2)
#pragma unroll
    for (int mi = 0; mi < 4; mi++) {
        int rbase = bm * 128 + wm * 64 + mi * 16 + g;
#pragma unroll
        for (int ni = 0; ni < 4; ni++) {
            int c = bn * 128 + wn * 32 + ni * 8 + 2 * tig;
#pragma unroll
            for (int half = 0; half < 2; half++) {
                int r = rbase + 8 * half;
                float v0 = acc[mi][ni][half * 2 + 0] + __ldg(bias + c);
                float v1 = acc[mi][ni][half * 2 + 1] + __ldg(bias + c + 1);
                size_t idx = (size_t)r * N + c;
                if (MODE == 0) {
                    *(__nv_bfloat162*)(outH + idx) = __floats2bfloat162_rn(v0, v1);
                } else if (MODE == 1) {
                    float2 res = *(const float2*)(resid + idx);
                    float2 o;
                    o.x = res.x + __ldg(gvec + c)     * v0;
                    o.y = res.y + __ldg(gvec + c + 1) * v1;
                    *(float2*)(outF + idx) = o;
                } else {
                    __nv_bfloat162 o = __floats2bfloat162_rn(gelu_fn(v0), gelu_fn(v1));
                    *(__nv_bfloat162*)(outH + idx) = o;
                }
            }
        }
    }
}

// ------------------- attention: kv_part[sp][d,e] = sum_{n in half sp} phi(k)*v ----
__global__ __launch_bounds__(256) void k_kv() {
    int sp = blockIdx.x;             // split 0/1
    int bh = blockIdx.y;
    int b = bh / NH, h = bh % NH;
    __shared__ float sk[64][68];
    __shared__ float sv[64][68];
    int tx = threadIdx.x & 15, ty = threadIdx.x >> 4;
    float acc[4][4];
#pragma unroll
    for (int i = 0; i < 4; i++)
#pragma unroll
        for (int j = 0; j < 4; j++) acc[i][j] = 0.f;

    const __nv_bfloat16* base = g_qkv + (size_t)b * HWN * (3 * CDIM);
    const int nlo = sp * (HWN / 2), nhi = nlo + HWN / 2;
    for (int n0 = nlo; n0 < nhi; n0 += 64) {
        for (int i = threadIdx.x; i < 4096; i += 256) {
            int nl = i >> 6, d = i & 63;
            const __nv_bfloat16* rowp = base + (size_t)(n0 + nl) * (3 * CDIM) + h * HD + d;
            sk[nl][d] = phi_fn(__bfloat162float(rowp[CDIM]));
            sv[nl][d] = __bfloat162float(rowp[2 * CDIM]);
        }
        __syncthreads();
#pragma unroll 8
        for (int nl = 0; nl < 64; nl++) {
            float4 kk = *(const float4*)&sk[nl][tx * 4];
            float4 vv = *(const float4*)&sv[nl][ty * 4];
            acc[0][0] += kk.x * vv.x; acc[0][1] += kk.x * vv.y; acc[0][2] += kk.x * vv.z; acc[0][3] += kk.x * vv.w;
            acc[1][0] += kk.y * vv.x; acc[1][1] += kk.y * vv.y; acc[1][2] += kk.y * vv.z; acc[1][3] += kk.y * vv.w;
            acc[2][0] += kk.z * vv.x; acc[2][1] += kk.z * vv.y; acc[2][2] += kk.z * vv.z; acc[2][3] += kk.z * vv.w;
            acc[3][0] += kk.w * vv.x; acc[3][1] += kk.w * vv.y; acc[3][2] += kk.w * vv.z; acc[3][3] += kk.w * vv.w;
        }
        __syncthreads();
    }
    float* dst = g_kvp + ((size_t)sp * (BATCH * NH) + bh) * (HD * HD);
#pragma unroll
    for (int i = 0; i < 4; i++)
#pragma unroll
        for (int j = 0; j < 4; j++)
            dst[(tx * 4 + i) * HD + (ty * 4 + j)] = acc[i][j];
}

// ------------------- attention: o[n,e] = sum_d phi(q[n,d]) * kv[d,e] -------------------
__global__ __launch_bounds__(256) void k_ov() {
    int bh = blockIdx.y;
    int b = bh / NH, h = bh % NH;
    int t0 = blockIdx.x * 64;
    __shared__ float sq[64][68];
    __shared__ float skv[64][68];
    const float* kv0 = g_kvp + (size_t)bh * (HD * HD);
    const float* kv1 = g_kvp + ((size_t)(BATCH * NH) + bh) * (HD * HD);
    for (int i = threadIdx.x; i < 4096; i += 256) {
        int tl = i >> 6, d = i & 63;
        sq[tl][d] = phi_fn(__bfloat162float(
            g_qkv[((size_t)(b * HWN + t0 + tl)) * (3 * CDIM) + h * HD + d]));
        skv[tl][d] = kv0[i] + kv1[i];
    }
    __syncthreads();
    int tx = threadIdx.x & 15, ty = threadIdx.x >> 4;
    float acc[4][4];
#pragma unroll
    for (int i = 0; i < 4; i++)
#pragma unroll
        for (int j = 0; j < 4; j++) acc[i][j] = 0.f;
#pragma unroll 8
    for (int d = 0; d < 64; d++) {
        float4 kvv = *(const float4*)&skv[d][tx * 4];
        float q0 = sq[ty * 4 + 0][d];
        float q1 = sq[ty * 4 + 1][d];
        float q2 = sq[ty * 4 + 2][d];
        float q3 = sq[ty * 4 + 3][d];
        acc[0][0] += q0 * kvv.x; acc[0][1] += q0 * kvv.y; acc[0][2] += q0 * kvv.z; acc[0][3] += q0 * kvv.w;
        acc[1][0] += q1 * kvv.x; acc[1][1] += q1 * kvv.y; acc[1][2] += q1 * kvv.z; acc[1][3] += q1 * kvv.w;
        acc[2][0] += q2 * kvv.x; acc[2][1] += q2 * kvv.y; acc[2][2] += q2 * kvv.z; acc[2][3] += q2 * kvv.w;
        acc[3][0] += q3 * kvv.x; acc[3][1] += q3 * kvv.y; acc[3][2] += q3 * kvv.z; acc[3][3] += q3 * kvv.w;
    }
#pragma unroll
    for (int i = 0; i < 4; i++) {
        size_t m = (size_t)b * HWN + t0 + ty * 4 + i;
        size_t cb = m * CDIM + h * HD + tx * 4;
        *(__nv_bfloat162*)(g_o + cb)     = __floats2bfloat162_rn(acc[i][0], acc[i][1]);
        *(__nv_bfloat162*)(g_o + cb + 2) = __floats2bfloat162_rn(acc[i][2], acc[i][3]);
    }
}

// ------------------- host -------------------
extern "C" void kernel_launch(void* const* d_in, const int* in_sizes, int n_in,
                              void* d_out, int out_size) {
    const float* x        = (const float*)d_in[0];
    const float* rel_bias = (const float*)d_in[1];
    const float* rpe_sc   = (const float*)d_in[2];
    const float* w_qkv    = (const float*)d_in[3];
    const float* b_qkv    = (const float*)d_in[4];
    const float* w_out    = (const float*)d_in[5];
    const float* b_out    = (const float*)d_in[6];
    const float* ln1_w    = (const float*)d_in[7];
    const float* ln1_b    = (const float*)d_in[8];
    const float* ln2_w    = (const float*)d_in[9];
    const float* ln2_b    = (const float*)d_in[10];
    const float* w1       = (const float*)d_in[11];
    const float* b1       = (const float*)d_in[12];
    const float* w2       = (const float*)d_in[13];
    const float* b2       = (const float*)d_in[14];
    const float* g_attn   = (const float*)d_in[15];
    const float* g_ffn    = (const float*)d_in[16];

    void *p_tok, *p_xn, *p_qkv, *p_o, *p_hb, *p_wqkv, *p_wout, *p_w1, *p_w2;
    cudaGetSymbolAddress(&p_tok,  g_tok);
    cudaGetSymbolAddress(&p_xn,   g_xn);
    cudaGetSymbolAddress(&p_qkv,  g_qkv);
    cudaGetSymbolAddress(&p_o,    g_o);
    cudaGetSymbolAddress(&p_hb,   g_hb);
    cudaGetSymbolAddress(&p_wqkv, g_wqkv);
    cudaGetSymbolAddress(&p_wout, g_wout);
    cudaGetSymbolAddress(&p_w1,   g_w1);
    cudaGetSymbolAddress(&p_w2,   g_w2);

    cudaFuncSetAttribute(k_gemm<0>, cudaFuncAttributeMaxDynamicSharedMemorySize, GEMM_SMEM);
    cudaFuncSetAttribute(k_gemm<1>, cudaFuncAttributeMaxDynamicSharedMemorySize, GEMM_SMEM);
    cudaFuncSetAttribute(k_gemm<2>, cudaFuncAttributeMaxDynamicSharedMemorySize, GEMM_SMEM);
    cudaFuncSetAttribute(k_gemm<3>, cudaFuncAttributeMaxDynamicSharedMemorySize, GEMM_SMEM);
    cudaFuncSetAttribute(k_rpe_ln, cudaFuncAttributeMaxDynamicSharedMemorySize, RPELN_SMEM);

    // fused RPE + tokenize + LN1 (writes g_tok and g_xn)
    k_rpe_ln<<<dim3(HWN / 32, BATCH), 256, RPELN_SMEM>>>(x, rel_bias, rpe_sc, ln1_w, ln1_b);

    // weight transposes
    k_wtrans<<<dim3(CDIM / 32, 3 * CDIM / 32), dim3(32, 8)>>>(w_qkv, (__nv_bfloat16*)p_wqkv, CDIM, 3 * CDIM);
    k_wtrans<<<dim3(CDIM / 32, CDIM / 32),     dim3(32, 8)>>>(w_out, (__nv_bfloat16*)p_wout, CDIM, CDIM);
    k_wtrans<<<dim3(CDIM / 32, HID / 32),      dim3(32, 8)>>>(w1,    (__nv_bfloat16*)p_w1,   CDIM, HID);
    k_wtrans<<<dim3(HID / 32, CDIM / 32),      dim3(32, 8)>>>(w2,    (__nv_bfloat16*)p_w2,   HID, CDIM);

    // QKV projection (bf16 out)
    k_gemm<0><<<dim3(3 * CDIM / 128, MT / 128), 256, GEMM_SMEM>>>(
        (const __nv_bfloat16*)p_xn, (const __nv_bfloat16*)p_wqkv,
        b_qkv, nullptr, nullptr, nullptr, (__nv_bfloat16*)p_qkv, CDIM, 3 * CDIM);

    // linear attention (split-2 kv)
    k_kv<<<dim3(2, BATCH * NH), 256>>>();
    k_ov<<<dim3(HWN / 64, BATCH * NH), 256>>>();

    // out projection + residual (token layout)
    k_gemm<1><<<dim3(CDIM / 128, MT / 128), 256, GEMM_SMEM>>>(
        (const __nv_bfloat16*)p_o, (const __nv_bfloat16*)p_wout,
        b_out, g_attn, (const float*)p_tok, (float*)p_tok, nullptr, CDIM, CDIM);

    // LN2 + MLP; MLP2 writes directly transposed to d_out (mode 3)
    k_ln<<<MT, 256>>>((const float*)p_tok, ln2_w, ln2_b, (__nv_bfloat16*)p_xn);
    k_gemm<2><<<dim3(HID / 128, MT / 128), 256, GEMM_SMEM>>>(
        (const __nv_bfloat16*)p_xn, (const __nv_bfloat16*)p_w1,
        b1, nullptr, nullptr, nullptr, (__nv_bfloat16*)p_hb, CDIM, HID);
    k_gemm<3><<<dim3(CDIM / 128, MT / 128), 256, GEMM_SMEM>>>(
        (const __nv_bfloat16*)p_hb, (const __nv_bfloat16*)p_w2,
        b2, g_ffn, (const float*)p_tok, (float*)d_out, nullptr, HID, CDIM);
}

// round 14
// speedup vs baseline: 1.0252x; 1.0252x over previous
#include <cuda_runtime.h>
#include <cuda_bf16.h>
#include <cstdint>
#include <cstddef>

#define BATCH 8
#define CDIM 768
#define HWN 4096
#define MT (BATCH*HWN)   // 32768 tokens
#define NH 12
#define HD 64
#define HID 3072

// ------------------- scratch (static device globals; no allocs) -------------------
__device__ float          g_tok[(size_t)MT*CDIM];
__device__ __nv_bfloat16  g_xn [(size_t)MT*CDIM];
__device__ __nv_bfloat16  g_qkv[(size_t)MT*3*CDIM];
__device__ float          g_kvp[2*BATCH*NH*HD*HD];    // split-2 partial kv
__device__ __nv_bfloat16  g_o  [(size_t)MT*CDIM];
__device__ __nv_bfloat16  g_hb [(size_t)MT*HID];
// transposed bf16 weights: (N, K) row-major (each row: K contiguous)
__device__ __nv_bfloat16  g_wqkv[(size_t)3*CDIM*CDIM];
__device__ __nv_bfloat16  g_wout[(size_t)CDIM*CDIM];
__device__ __nv_bfloat16  g_w1  [(size_t)HID*CDIM];
__device__ __nv_bfloat16  g_w2  [(size_t)CDIM*HID];

// ------------------- helpers -------------------
__device__ __forceinline__ float phi_fn(float x) { return x > 0.f ? x + 1.f : __expf(x); }
__device__ __forceinline__ float gelu_fn(float x) {
    return 0.5f * x * (1.f + erff(x * 0.70710678118654752f));
}
__device__ __forceinline__ uint32_t smem_u32(const void* p) {
    uint32_t a;
    asm("{ .reg .u64 t; cvta.to.shared.u64 t, %1; cvt.u32.u64 %0, t; }" : "=r"(a) : "l"(p));
    return a;
}
__device__ __forceinline__ void cpa16(uint32_t s, const void* g) {
    asm volatile("cp.async.cg.shared.global [%0], [%1], 16;" :: "r"(s), "l"(g));
}
__device__ __forceinline__ void ldsm4(uint32_t* r, uint32_t addr) {
    asm volatile("ldmatrix.sync.aligned.m8n8.x4.shared.b16 {%0,%1,%2,%3}, [%4];"
                 : "=r"(r[0]), "=r"(r[1]), "=r"(r[2]), "=r"(r[3]) : "r"(addr));
}

// ------------------- fused weight transpose: all 4 weights in ONE launch ----------
// Job j covers tiles [ofs[j], ofs[j+1]) of a flattened (K/32)x(N/32) tile grid.
// Tile t of job j: kt = t % (K/32), nt = t / (K/32).
__global__ void k_wtrans_all(const float* __restrict__ wq, const float* __restrict__ wo,
                             const float* __restrict__ w1, const float* __restrict__ w2) {
    __shared__ float t[32][33];
    // job tables (K, N, dst, src) resolved by range of blockIdx.x
    // grids: wq: 24x72=1728, wo: 24x24=576, w1: 24x96=2304, w2: 96x24=2304 -> total 6912
    int bid = blockIdx.x;
    const float* src; __nv_bfloat16* dst; int K, N, tile;
    if (bid < 1728)       { src = wq; dst = g_wqkv; K = CDIM; N = 3 * CDIM; tile = bid; }
    else if (bid < 2304)  { src = wo; dst = g_wout; K = CDIM; N = CDIM;     tile = bid - 1728; }
    else if (bid < 4608)  { src = w1; dst = g_w1;   K = CDIM; N = HID;      tile = bid - 2304; }
    else                  { src = w2; dst = g_w2;   K = HID;  N = CDIM;     tile = bid - 4608; }
    int ktiles = K >> 5;
    int k0 = (tile % ktiles) * 32, n0 = (tile / ktiles) * 32;
    for (int i = threadIdx.y; i < 32; i += 8)
        t[i][threadIdx.x] = src[(size_t)(k0 + i) * N + n0 + threadIdx.x];
    __syncthreads();
    for (int i = threadIdx.y; i < 32; i += 8)
        dst[(size_t)(n0 + i) * K + k0 + threadIdx.x] = __float2bfloat16(t[threadIdx.x][i]);
}

// ------------------- bicubic taps -------------------
__device__ __forceinline__ void cub_taps(int i, float* w, int* idx) {
    const float a = -0.75f;
    float src = (i + 0.5f) * 0.5f - 0.5f;
    float i0 = floorf(src);
#pragma unroll
    for (int t = 0; t < 4; t++) {
        float p = i0 + (float)(t - 1);
        float d = fabsf(src - p);
        float wt;
        if (d <= 1.f)       wt = ((a + 2.f) * d - (a + 3.f)) * d * d + 1.f;
        else if (d < 2.f)   wt = ((a * d - 5.f * a) * d + 8.f * a) * d - 4.f * a;
        else                wt = 0.f;
        w[t] = wt;
        int ip = (int)floorf(p);
        idx[t] = ip < 0 ? 0 : (ip > 31 ? 31 : ip);
    }
}

// ------------------- tokens: tok[b,n,c] = x[b,c,n] + scale*bicubic(rel)[c,n] -------
__global__ void k_rpe_tr(const float* __restrict__ x, const float* __restrict__ rel,
                         const float* __restrict__ rpe_scale) {
    __shared__ float tile[32][33];
    float sc = __ldg(rpe_scale);
    int b = blockIdx.z;
    int n0 = blockIdx.x * 32, c0 = blockIdx.y * 32;
    int n = n0 + threadIdx.x;
    int h = n >> 6, w = n & 63;
    float wh[4], ww[4]; int ih[4], iw[4];
    cub_taps(h, wh, ih);
    cub_taps(w, ww, iw);
    for (int i = threadIdx.y; i < 32; i += 8) {
        int c = c0 + i;
        const float* rb = rel + (size_t)c * 1024;
        float bias = 0.f;
#pragma unroll
        for (int ti = 0; ti < 4; ti++) {
            float rsum = 0.f;
#pragma unroll
            for (int tj = 0; tj < 4; tj++) rsum += ww[tj] * __ldg(rb + ih[ti] * 32 + iw[tj]);
            bias += wh[ti] * rsum;
        }
        tile[i][threadIdx.x] = x[((size_t)b * CDIM + c) * HWN + n] + sc * bias;
    }
    __syncthreads();
    for (int i = threadIdx.y; i < 32; i += 8) {
        int nn = n0 + i, c = c0 + threadIdx.x;
        g_tok[((size_t)b * HWN + nn) * CDIM + c] = tile[threadIdx.x][i];
    }
}

// ------------------- LayerNorm C=768 -> bf16 -------------------
__global__ void k_ln(const float* __restrict__ in, const float* __restrict__ w,
                     const float* __restrict__ bb, __nv_bfloat16* __restrict__ out) {
    __shared__ float red[16];
    int m = blockIdx.x;
    int t = threadIdx.x;
    const float* row = in + (size_t)m * CDIM;
    float v0 = row[t], v1 = row[t + 256], v2 = row[t + 512];
    float s = v0 + v1 + v2;
    float ss = v0 * v0 + v1 * v1 + v2 * v2;
#pragma unroll
    for (int off = 16; off > 0; off >>= 1) {
        s  += __shfl_xor_sync(0xffffffffu, s, off);
        ss += __shfl_xor_sync(0xffffffffu, ss, off);
    }
    int warp = t >> 5, lane = t & 31;
    if (lane == 0) { red[warp] = s; red[8 + warp] = ss; }
    __syncthreads();
    if (t < 32) {
        float a = (t < 8) ? red[t] : 0.f;
        float b2 = (t < 8) ? red[8 + t] : 0.f;
#pragma unroll
        for (int off = 4; off > 0; off >>= 1) {
            a  += __shfl_xor_sync(0xffffffffu, a, off);
            b2 += __shfl_xor_sync(0xffffffffu, b2, off);
        }
        if (t == 0) { red[0] = a; red[1] = b2; }
    }
    __syncthreads();
    float mean = red[0] * (1.f / CDIM);
    float var  = red[1] * (1.f / CDIM) - mean * mean;
    float r = rsqrtf(var + 1e-6f);
    __nv_bfloat16* orow = out + (size_t)m * CDIM;
    orow[t]       = __float2bfloat16((v0 - mean) * r * w[t]       + bb[t]);
    orow[t + 256] = __float2bfloat16((v1 - mean) * r * w[t + 256] + bb[t + 256]);
    orow[t + 512] = __float2bfloat16((v2 - mean) * r * w[t + 512] + bb[t + 512]);
}

// ------------------- HMMA GEMM: C(M,N) = A(M,K) @ Bt(N,K)^T -------------------
// 128x128 CTA tile, warp tile 64x32 (2x4 warps), K-step 64,
// 3-stage cp.async ring, ONE __syncthreads per K-step, copy issued BEFORE compute.
// MODE 0: outH = acc + bias[c]                       (bf16)
// MODE 1: outF = resid + gvec[c]*(acc + bias[c])     (fp32, token layout)
// MODE 2: outH = gelu(acc + bias[c])                 (bf16)
// MODE 3: out (B,C,H,W) = resid + gvec[c]*(acc+bias) TRANSPOSED via smem tile
#define ROWB 144u
#define B_OFF 18432u
#define STG_BYTES 36864u
#define GEMM_SMEM (3*36864)

template<int MODE>
__global__ __launch_bounds__(256, 2) void k_gemm(
    const __nv_bfloat16* __restrict__ A, const __nv_bfloat16* __restrict__ Bt,
    const float* __restrict__ bias, const float* __restrict__ gvec,
    const float* __restrict__ resid, float* __restrict__ outF,
    __nv_bfloat16* __restrict__ outH, int K, int N)
{
    extern __shared__ char smem[];
    const uint32_t sbase = smem_u32(smem);
    const int tid = threadIdx.x;
    const int warp = tid >> 5, lane = tid & 31;
    const int wm = warp >> 2, wn = warp & 3;          // 2x4 warps, warp tile 64x32
    const int g = lane >> 2, tig = lane & 3;
    const int bm = blockIdx.y, bn = blockIdx.x;

    float acc[4][4][4];
#pragma unroll
    for (int a = 0; a < 4; a++)
#pragma unroll
        for (int b = 0; b < 4; b++)
#pragma unroll
            for (int c = 0; c < 4; c++) acc[a][b][c] = 0.f;

    const __nv_bfloat16* Ab = A  + (size_t)(bm * 128) * K;
    const __nv_bfloat16* Bb = Bt + (size_t)(bn * 128) * K;
    const int nk = K >> 6;

    const uint32_t aoff = (uint32_t)(wm * 64 + (lane & 15)) * ROWB + (uint32_t)(lane >> 4) * 16;
    const uint32_t boff = B_OFF
                        + (uint32_t)(wn * 32 + (lane & 7) + ((lane >> 4) & 1) * 8) * ROWB
                        + (uint32_t)((lane >> 3) & 1) * 16;

#define COPY_STAGE(buf, k0)                                                          \
    do {                                                                             \
        uint32_t sd = sbase + (uint32_t)(buf) * STG_BYTES;                           \
        _Pragma("unroll")                                                            \
        for (int i = 0; i < 4; i++) {          /* A: 1024 chunks */                  \
            int idx = tid + i * 256; int r = idx >> 3, c4 = idx & 7;                 \
            cpa16(sd + (uint32_t)r * ROWB + (uint32_t)c4 * 16,                       \
                  Ab + (size_t)r * K + (k0) + c4 * 8);                               \
        }                                                                            \
        _Pragma("unroll")                                                            \
        for (int i = 0; i < 4; i++) {          /* B: 1024 chunks */                  \
            int idx = tid + i * 256; int r = idx >> 3, c4 = idx & 7;                 \
            cpa16(sd + B_OFF + (uint32_t)r * ROWB + (uint32_t)c4 * 16,               \
                  Bb + (size_t)r * K + (k0) + c4 * 8);                               \
        }                                                                            \
    } while (0)

    COPY_STAGE(0, 0);
    asm volatile("cp.async.commit_group;" ::: "memory");
    COPY_STAGE(1, 64);
    asm volatile("cp.async.commit_group;" ::: "memory");

    int stg = 0;   // buffer holding stage s
    for (int s = 0; s < nk; s++) {
        asm volatile("cp.async.wait_group 1;" ::: "memory");
        __syncthreads();   // stage s visible; all warps done with buffer (s+2)%3

        int nb = stg + 2; if (nb >= 3) nb -= 3;
        if (s + 2 < nk) COPY_STAGE(nb, (s + 2) << 6);
        asm volatile("cp.async.commit_group;" ::: "memory");   // unconditional: group numbering

        uint32_t sb0 = sbase + (uint32_t)stg * STG_BYTES;
#pragma unroll
        for (int kk = 0; kk < 4; kk++) {        // four k16 sub-steps
            uint32_t af[4][4], bfr[2][4];
#pragma unroll
            for (int mi = 0; mi < 4; mi++)
                ldsm4(af[mi], sb0 + aoff + (uint32_t)(mi * 16) * ROWB + kk * 32);
#pragma unroll
            for (int p = 0; p < 2; p++)
                ldsm4(bfr[p], sb0 + boff + (uint32_t)(p * 16) * ROWB + kk * 32);
#pragma unroll
            for (int mi = 0; mi < 4; mi++)
#pragma unroll
                for (int ni = 0; ni < 4; ni++) {
                    const int p = ni >> 1, q = (ni & 1) * 2;
                    asm volatile(
                        "mma.sync.aligned.m16n8k16.row.col.f32.bf16.bf16.f32 "
                        "{%0,%1,%2,%3}, {%4,%5,%6,%7}, {%8,%9}, {%0,%1,%2,%3};"
                        : "+f"(acc[mi][ni][0]), "+f"(acc[mi][ni][1]),
                          "+f"(acc[mi][ni][2]), "+f"(acc[mi][ni][3])
                        : "r"(af[mi][0]), "r"(af[mi][1]), "r"(af[mi][2]), "r"(af[mi][3]),
                          "r"(bfr[p][q]), "r"(bfr[p][q + 1]));
                }
        }
        stg++; if (stg == 3) stg = 0;
    }
#undef COPY_STAGE

    if (MODE == 3) {
        // transposed epilogue: stage (resid + g*(acc+bias)) tile in smem, write
        // coalesced along n to (B,C,H,W) output. Tile never crosses batch bound.
        float* smf = (float*)smem;
        __syncthreads();   // mainloop smem fully consumed by all warps
#pragma unroll
        for (int mi = 0; mi < 4; mi++) {
            int rl = wm * 64 + mi * 16 + g;
#pragma unroll
            for (int ni = 0; ni < 4; ni++) {
                int cl = wn * 32 + ni * 8 + 2 * tig;
                int c = bn * 128 + cl;
#pragma unroll
                for (int half = 0; half < 2; half++) {
                    int r = rl + 8 * half;
                    float v0 = acc[mi][ni][half * 2 + 0] + __ldg(bias + c);
                    float v1 = acc[mi][ni][half * 2 + 1] + __ldg(bias + c + 1);
                    size_t idx = (size_t)(bm * 128 + r) * N + c;
                    float2 res = *(const float2*)(resid + idx);
                    smf[cl * 132 + r]       = res.x + __ldg(gvec + c)     * v0;
                    smf[(cl + 1) * 132 + r] = res.y + __ldg(gvec + c + 1) * v1;
                }
            }
        }
        __syncthreads();
        int b  = (bm * 128) >> 12;         // /HWN
        int n0 = (bm * 128) & 4095;
#pragma unroll
        for (int i = 0; i < 16; i++) {
            int idx = tid + i * 256;
            int cl = idx >> 5, q = idx & 31;         // each warp: one full c-row
            float4 v = *(float4*)&smf[cl * 132 + q * 4];
            *(float4*)(outF + (((size_t)b * CDIM + bn * 128 + cl) << 12) + n0 + q * 4) = v;
        }
        return;
    }

    // epilogue (MODES 0/1/2)
#pragma unroll
    for (int mi = 0; mi < 4; mi++) {
        int rbase = bm * 128 + wm * 64 + mi * 16 + g;
#pragma unroll
        for (int ni = 0; ni < 4; ni++) {
            int c = bn * 128 + wn * 32 + ni * 8 + 2 * tig;
#pragma unroll
            for (int half = 0; half < 2; half++) {
                int r = rbase + 8 * half;
                float v0 = acc[mi][ni][half * 2 + 0] + __ldg(bias + c);
                float v1 = acc[mi][ni][half * 2 + 1] + __ldg(bias + c + 1);
                size_t idx = (size_t)r * N + c;
                if (MODE == 0) {
                    *(__nv_bfloat162*)(outH + idx) = __floats2bfloat162_rn(v0, v1);
                } else if (MODE == 1) {
                    float2 res = *(const float2*)(resid + idx);
                    float2 o;
                    o.x = res.x + __ldg(gvec + c)     * v0;
                    o.y = res.y + __ldg(gvec + c + 1) * v1;
                    *(float2*)(outF + idx) = o;
                } else {
                    __nv_bfloat162 o = __floats2bfloat162_rn(gelu_fn(v0), gelu_fn(v1));
                    *(__nv_bfloat162*)(outH + idx) = o;
                }
            }
        }
    }
}

// ------------------- attention: kv_part[sp][d,e] = sum_{n in half sp} phi(k)*v ----
__global__ __launch_bounds__(256) void k_kv() {
    int sp = blockIdx.x;             // split 0/1
    int bh = blockIdx.y;
    int b = bh / NH, h = bh % NH;
    __shared__ float sk[64][68];
    __shared__ float sv[64][68];
    int tx = threadIdx.x & 15, ty = threadIdx.x >> 4;
    float acc[4][4];
#pragma unroll
    for (int i = 0; i < 4; i++)
#pragma unroll
        for (int j = 0; j < 4; j++) acc[i][j] = 0.f;

    const __nv_bfloat16* base = g_qkv + (size_t)b * HWN * (3 * CDIM);
    const int nlo = sp * (HWN / 2), nhi = nlo + HWN / 2;
    for (int n0 = nlo; n0 < nhi; n0 += 64) {
        for (int i = threadIdx.x; i < 4096; i += 256) {
            int nl = i >> 6, d = i & 63;
            const __nv_bfloat16* rowp = base + (size_t)(n0 + nl) * (3 * CDIM) + h * HD + d;
            sk[nl][d] = phi_fn(__bfloat162float(rowp[CDIM]));
            sv[nl][d] = __bfloat162float(rowp[2 * CDIM]);
        }
        __syncthreads();
#pragma unroll 8
        for (int nl = 0; nl < 64; nl++) {
            float4 kk = *(const float4*)&sk[nl][tx * 4];
            float4 vv = *(const float4*)&sv[nl][ty * 4];
            acc[0][0] += kk.x * vv.x; acc[0][1] += kk.x * vv.y; acc[0][2] += kk.x * vv.z; acc[0][3] += kk.x * vv.w;
            acc[1][0] += kk.y * vv.x; acc[1][1] += kk.y * vv.y; acc[1][2] += kk.y * vv.z; acc[1][3] += kk.y * vv.w;
            acc[2][0] += kk.z * vv.x; acc[2][1] += kk.z * vv.y; acc[2][2] += kk.z * vv.z; acc[2][3] += kk.z * vv.w;
            acc[3][0] += kk.w * vv.x; acc[3][1] += kk.w * vv.y; acc[3][2] += kk.w * vv.z; acc[3][3] += kk.w * vv.w;
        }
        __syncthreads();
    }
    float* dst = g_kvp + ((size_t)sp * (BATCH * NH) + bh) * (HD * HD);
#pragma unroll
    for (int i = 0; i < 4; i++)
#pragma unroll
        for (int j = 0; j < 4; j++)
            dst[(tx * 4 + i) * HD + (ty * 4 + j)] = acc[i][j];
}

// ------------------- attention: o[n,e] = sum_d phi(q[n,d]) * kv[d,e] -------------------
__global__ __launch_bounds__(256) void k_ov() {
    int bh = blockIdx.y;
    int b = bh / NH, h = bh % NH;
    int t0 = blockIdx.x * 64;
    __shared__ float sq[64][68];
    __shared__ float skv[64][68];
    const float* kv0 = g_kvp + (size_t)bh * (HD * HD);
    const float* kv1 = g_kvp + ((size_t)(BATCH * NH) + bh) * (HD * HD);
    for (int i = threadIdx.x; i < 4096; i += 256) {
        int tl = i >> 6, d = i & 63;
        sq[tl][d] = phi_fn(__bfloat162float(
            g_qkv[((size_t)(b * HWN + t0 + tl)) * (3 * CDIM) + h * HD + d]));
        skv[tl][d] = kv0[i] + kv1[i];
    }
    __syncthreads();
    int tx = threadIdx.x & 15, ty = threadIdx.x >> 4;
    float acc[4][4];
#pragma unroll
    for (int i = 0; i < 4; i++)
#pragma unroll
        for (int j = 0; j < 4; j++) acc[i][j] = 0.f;
#pragma unroll 8
    for (int d = 0; d < 64; d++) {
        float4 kvv = *(const float4*)&skv[d][tx * 4];
        float q0 = sq[ty * 4 + 0][d];
        float q1 = sq[ty * 4 + 1][d];
        float q2 = sq[ty * 4 + 2][d];
        float q3 = sq[ty * 4 + 3][d];
        acc[0][0] += q0 * kvv.x; acc[0][1] += q0 * kvv.y; acc[0][2] += q0 * kvv.z; acc[0][3] += q0 * kvv.w;
        acc[1][0] += q1 * kvv.x; acc[1][1] += q1 * kvv.y; acc[1][2] += q1 * kvv.z; acc[1][3] += q1 * kvv.w;
        acc[2][0] += q2 * kvv.x; acc[2][1] += q2 * kvv.y; acc[2][2] += q2 * kvv.z; acc[2][3] += q2 * kvv.w;
        acc[3][0] += q3 * kvv.x; acc[3][1] += q3 * kvv.y; acc[3][2] += q3 * kvv.z; acc[3][3] += q3 * kvv.w;
    }
#pragma unroll
    for (int i = 0; i < 4; i++) {
        size_t m = (size_t)b * HWN + t0 + ty * 4 + i;
        size_t cb = m * CDIM + h * HD + tx * 4;
        *(__nv_bfloat162*)(g_o + cb)     = __floats2bfloat162_rn(acc[i][0], acc[i][1]);
        *(__nv_bfloat162*)(g_o + cb + 2) = __floats2bfloat162_rn(acc[i][2], acc[i][3]);
    }
}

// ------------------- host -------------------
extern "C" void kernel_launch(void* const* d_in, const int* in_sizes, int n_in,
                              void* d_out, int out_size) {
    const float* x        = (const float*)d_in[0];
    const float* rel_bias = (const float*)d_in[1];
    const float* rpe_sc   = (const float*)d_in[2];
    const float* w_qkv    = (const float*)d_in[3];
    const float* b_qkv    = (const float*)d_in[4];
    const float* w_out    = (const float*)d_in[5];
    const float* b_out    = (const float*)d_in[6];
    const float* ln1_w    = (const float*)d_in[7];
    const float* ln1_b    = (const float*)d_in[8];
    const float* ln2_w    = (const float*)d_in[9];
    const float* ln2_b    = (const float*)d_in[10];
    const float* w1       = (const float*)d_in[11];
    const float* b1       = (const float*)d_in[12];
    const float* w2       = (const float*)d_in[13];
    const float* b2       = (const float*)d_in[14];
    const float* g_attn   = (const float*)d_in[15];
    const float* g_ffn    = (const float*)d_in[16];

    void *p_tok, *p_xn, *p_qkv, *p_o, *p_hb, *p_wqkv, *p_wout, *p_w1, *p_w2;
    cudaGetSymbolAddress(&p_tok,  g_tok);
    cudaGetSymbolAddress(&p_xn,   g_xn);
    cudaGetSymbolAddress(&p_qkv,  g_qkv);
    cudaGetSymbolAddress(&p_o,    g_o);
    cudaGetSymbolAddress(&p_hb,   g_hb);
    cudaGetSymbolAddress(&p_wqkv, g_wqkv);
    cudaGetSymbolAddress(&p_wout, g_wout);
    cudaGetSymbolAddress(&p_w1,   g_w1);
    cudaGetSymbolAddress(&p_w2,   g_w2);

    cudaFuncSetAttribute(k_gemm<0>, cudaFuncAttributeMaxDynamicSharedMemorySize, GEMM_SMEM);
    cudaFuncSetAttribute(k_gemm<1>, cudaFuncAttributeMaxDynamicSharedMemorySize, GEMM_SMEM);
    cudaFuncSetAttribute(k_gemm<2>, cudaFuncAttributeMaxDynamicSharedMemorySize, GEMM_SMEM);
    cudaFuncSetAttribute(k_gemm<3>, cudaFuncAttributeMaxDynamicSharedMemorySize, GEMM_SMEM);

    // RPE + tokenization (bicubic fused)
    k_rpe_tr<<<dim3(HWN / 32, CDIM / 32, BATCH), dim3(32, 8)>>>(x, rel_bias, rpe_sc);

    // all weight transposes in ONE launch (6912 tiles)
    k_wtrans_all<<<6912, dim3(32, 8)>>>(w_qkv, w_out, w1, w2);

    // LN1 + QKV projection (bf16 out)
    k_ln<<<MT, 256>>>((const float*)p_tok, ln1_w, ln1_b, (__nv_bfloat16*)p_xn);
    k_gemm<0><<<dim3(3 * CDIM / 128, MT / 128), 256, GEMM_SMEM>>>(
        (const __nv_bfloat16*)p_xn, (const __nv_bfloat16*)p_wqkv,
        b_qkv, nullptr, nullptr, nullptr, (__nv_bfloat16*)p_qkv, CDIM, 3 * CDIM);

    // linear attention (split-2 kv)
    k_kv<<<dim3(2, BATCH * NH), 256>>>();
    k_ov<<<dim3(HWN / 64, BATCH * NH), 256>>>();

    // out projection + residual (token layout)
    k_gemm<1><<<dim3(CDIM / 128, MT / 128), 256, GEMM_SMEM>>>(
        (const __nv_bfloat16*)p_o, (const __nv_bfloat16*)p_wout,
        b_out, g_attn, (const float*)p_tok, (float*)p_tok, nullptr, CDIM, CDIM);

    // LN2 + MLP; MLP2 writes directly transposed to d_out (mode 3)
    k_ln<<<MT, 256>>>((const float*)p_tok, ln2_w, ln2_b, (__nv_bfloat16*)p_xn);
    k_gemm<2><<<dim3(HID / 128, MT / 128), 256, GEMM_SMEM>>>(
        (const __nv_bfloat16*)p_xn, (const __nv_bfloat16*)p_w1,
        b1, nullptr, nullptr, nullptr, (__nv_bfloat16*)p_hb, CDIM, HID);
    k_gemm<3><<<dim3(CDIM / 128, MT / 128), 256, GEMM_SMEM>>>(
        (const __nv_bfloat16*)p_hb, (const __nv_bfloat16*)p_w2,
        b2, g_ffn, (const float*)p_tok, (float*)d_out, nullptr, HID, CDIM);
}